// round 2
// baseline (speedup 1.0000x reference)
#include <cuda_runtime.h>
#include <math.h>

#define B_SZ   2048
#define T_SZ   512
#define D_IN   64
#define H_SZ   128
#define D_OUT  64
#define M_TILE 16
#define NTHREADS 256
#define NSTEPS (T_SZ - 1)
#define BSTRIDE 256   // dup'd activation row stride (floats)

// SMEM layout (floats):
//  [0      .. 16384)  Whh_t  (k-major: Whh_t[k*H+j] = W_hh[j*H+k])
//  [16384  .. 32768)  W1t    (reused post-loop for W_out_t [k*64+j])
//  [32768  .. 49152)  W2t
//  [49152  .. 53248)  buf0   [16][256]  duplicated pairs (a,a)
//  [53248  .. 57344)  buf1   [16][256]
//  [57344  .. 57472)  v_s
//  [57472  .. 57600)  c_s
//  [57600  .. 57728)  b1_s
//  [57728  .. 57856)  b2_s
//  [57856  .. 57872)  xs
#define OFF_WHH 0
#define OFF_W1  16384
#define OFF_W2  32768
#define OFF_B0  49152
#define OFF_B1  53248
#define OFF_V   57344
#define OFF_C   57472
#define OFF_BB1 57600
#define OFF_BB2 57728
#define OFF_XS  57856
#define SMEM_FLOATS 57872
#define SMEM_BYTES  (SMEM_FLOATS * 4)   // 231488 <= 232448 (227KB opt-in)

typedef unsigned long long u64;

__device__ __forceinline__ u64 pk(float a, float b) {
    u64 r;
    asm("mov.b64 %0, {%1, %2};" : "=l"(r) : "f"(a), "f"(b));
    return r;
}
__device__ __forceinline__ void upk(u64 v, float& a, float& b) {
    asm("mov.b64 {%0, %1}, %2;" : "=f"(a), "=f"(b) : "l"(v));
}
__device__ __forceinline__ void ffma2(u64& d, u64 a, u64 b) {
    asm("fma.rn.f32x2 %0, %1, %2, %0;" : "+l"(d) : "l"(a), "l"(b));
}

// acc[ri] (col pair c0,c0+1; rows rbase..rbase+3) += buf_dup @ Wt
__device__ __forceinline__ void gemm2(const float* __restrict__ Wt,
                                      const float* __restrict__ buf,
                                      int rbase, int c0, u64 acc[4]) {
    const float* a0 = buf + rbase * BSTRIDE;
#pragma unroll 4
    for (int k = 0; k < H_SZ; k += 4) {
        const u64 w0 = *reinterpret_cast<const u64*>(Wt + (k + 0) * H_SZ + c0);
        const u64 w1 = *reinterpret_cast<const u64*>(Wt + (k + 1) * H_SZ + c0);
        const u64 w2 = *reinterpret_cast<const u64*>(Wt + (k + 2) * H_SZ + c0);
        const u64 w3 = *reinterpret_cast<const u64*>(Wt + (k + 3) * H_SZ + c0);
#pragma unroll
        for (int ri = 0; ri < 4; ri++) {
            const ulonglong2 p0 = *reinterpret_cast<const ulonglong2*>(a0 + ri * BSTRIDE + 2 * k);
            const ulonglong2 p1 = *reinterpret_cast<const ulonglong2*>(a0 + ri * BSTRIDE + 2 * k + 4);
            ffma2(acc[ri], p0.x, w0);
            ffma2(acc[ri], p0.y, w1);
            ffma2(acc[ri], p1.x, w2);
            ffma2(acc[ri], p1.y, w3);
        }
    }
}

__device__ __forceinline__ void stage_dup(float* __restrict__ bp, int rbase, int c0,
                                          const float v[4][2]) {
#pragma unroll
    for (int ri = 0; ri < 4; ri++) {
        *reinterpret_cast<float4*>(bp + (rbase + ri) * BSTRIDE + 2 * c0) =
            make_float4(v[ri][0], v[ri][0], v[ri][1], v[ri][1]);
    }
}

__device__ __forceinline__ float silu_f(float v) {
    return v / (1.0f + __expf(-v));
}

// out = f(in) = silu(in @ W1^T + b1) @ W2^T + b2
__device__ __forceinline__ void feval2(const float in[4][2], float out[4][2],
                                       const float* __restrict__ W1t,
                                       const float* __restrict__ W2t,
                                       u64 bb1, u64 bb2,
                                       float* __restrict__ buf0,
                                       float* __restrict__ buf1,
                                       int& p, int rbase, int c0) {
    float* bp = p ? buf1 : buf0;
    stage_dup(bp, rbase, c0, in);
    __syncthreads();

    u64 acc[4];
#pragma unroll
    for (int ri = 0; ri < 4; ri++) acc[ri] = bb1;
    gemm2(W1t, bp, rbase, c0, acc);

    float z[4][2];
#pragma unroll
    for (int ri = 0; ri < 4; ri++) {
        upk(acc[ri], z[ri][0], z[ri][1]);
        z[ri][0] = silu_f(z[ri][0]);
        z[ri][1] = silu_f(z[ri][1]);
    }

    p ^= 1;
    bp = p ? buf1 : buf0;
    stage_dup(bp, rbase, c0, z);
    __syncthreads();

#pragma unroll
    for (int ri = 0; ri < 4; ri++) acc[ri] = bb2;
    gemm2(W2t, bp, rbase, c0, acc);
#pragma unroll
    for (int ri = 0; ri < 4; ri++) upk(acc[ri], out[ri][0], out[ri][1]);
    p ^= 1;
}

__global__ void __launch_bounds__(NTHREADS, 1)
rnnode_kernel(const float* __restrict__ x, const float* __restrict__ span,
              const float* __restrict__ W_emb, const float* __restrict__ b_emb,
              const float* __restrict__ W_ih, const float* __restrict__ b_ih,
              const float* __restrict__ W_hh, const float* __restrict__ b_hh,
              const float* __restrict__ W1, const float* __restrict__ b1,
              const float* __restrict__ W2, const float* __restrict__ b2,
              const float* __restrict__ W_out, const float* __restrict__ b_out,
              float* __restrict__ out) {
    extern __shared__ float sm[];
    float* Whh_t = sm + OFF_WHH;
    float* W1t   = sm + OFF_W1;
    float* W2t   = sm + OFF_W2;
    float* buf0  = sm + OFF_B0;
    float* buf1  = sm + OFF_B1;
    float* v_s   = sm + OFF_V;
    float* c_s   = sm + OFF_C;
    float* b1_s  = sm + OFF_BB1;
    float* b2_s  = sm + OFF_BB2;
    float* xs    = sm + OFF_XS;

    const int tid = threadIdx.x;
    const int b0  = blockIdx.x * M_TILE;

    // Weights transposed to k-major.
    for (int i = tid; i < H_SZ * H_SZ; i += NTHREADS) {
        const int j = i >> 7, k = i & 127;
        Whh_t[k * H_SZ + j] = W_hh[i];
        W1t[k * H_SZ + j]   = W1[i];
        W2t[k * H_SZ + j]   = W2[i];
    }
    // Fold input path: u[b,t,:] = x[b,t]*v + c, c absorbing b_ih + b_hh.
    if (tid < H_SZ) {
        float vv = 0.0f, cc = 0.0f;
        for (int d = 0; d < D_IN; d++) {
            const float w = W_ih[tid * D_IN + d];
            vv = fmaf(w, W_emb[d], vv);
            cc = fmaf(w, b_emb[d], cc);
        }
        v_s[tid]  = vv;
        c_s[tid]  = cc + b_ih[tid] + b_hh[tid];
        b1_s[tid] = b1[tid];
        b2_s[tid] = b2[tid];
    }
    __syncthreads();

    const int wid  = tid >> 5;
    const int lane = tid & 31;
    const int rowg = lane >> 3;          // 0..3  (phase-uniform -> a-load broadcast)
    const int colg = lane & 7;           // 0..7
    const int rbase = rowg * 4;          // rows rbase..rbase+3
    const int c0    = wid * 16 + colg * 2;  // col pair c0, c0+1

    // Hoisted per-thread constants
    const float vv0 = v_s[c0],     vv1 = v_s[c0 + 1];
    const float cc0 = c_s[c0],     cc1 = c_s[c0 + 1];
    const u64 bb1 = pk(b1_s[c0], b1_s[c0 + 1]);
    const u64 bb2 = pk(b2_s[c0], b2_s[c0 + 1]);

    float h[4][2];
#pragma unroll
    for (int ri = 0; ri < 4; ri++) { h[ri][0] = 0.0f; h[ri][1] = 0.0f; }

    int p = 0;

    for (int t = 0; t < NSTEPS; t++) {
        const float dt  = __ldg(span + t + 1) - __ldg(span + t);
        const float dt3 = dt * (1.0f / 3.0f);

        // ---- RNN jump: h = tanh(x*v + c + h @ W_hh^T) ----
        float* bp = p ? buf1 : buf0;
        stage_dup(bp, rbase, c0, h);
        if (tid < M_TILE) xs[tid] = x[(size_t)(b0 + tid) * T_SZ + t];
        __syncthreads();

        u64 acc[4];
#pragma unroll
        for (int ri = 0; ri < 4; ri++) {
            const float xv = xs[rbase + ri];
            acc[ri] = pk(fmaf(xv, vv0, cc0), fmaf(xv, vv1, cc1));
        }
        gemm2(Whh_t, bp, rbase, c0, acc);
        p ^= 1;
#pragma unroll
        for (int ri = 0; ri < 4; ri++) {
            float a0, a1;
            upk(acc[ri], a0, a1);
            h[ri][0] = tanhf(a0);
            h[ri][1] = tanhf(a1);
        }

        // ---- RK4 (3/8 rule) ----
        float k1v[4][2], k2v[4][2], kv[4][2], y[4][2], ksum[4][2];

        feval2(h, k1v, W1t, W2t, bb1, bb2, buf0, buf1, p, rbase, c0);
#pragma unroll
        for (int ri = 0; ri < 4; ri++)
#pragma unroll
            for (int c = 0; c < 2; c++)
                y[ri][c] = fmaf(dt3, k1v[ri][c], h[ri][c]);

        feval2(y, k2v, W1t, W2t, bb1, bb2, buf0, buf1, p, rbase, c0);
#pragma unroll
        for (int ri = 0; ri < 4; ri++)
#pragma unroll
            for (int c = 0; c < 2; c++)
                y[ri][c] = fmaf(dt, k2v[ri][c], fmaf(-dt3, k1v[ri][c], h[ri][c]));

        feval2(y, kv, W1t, W2t, bb1, bb2, buf0, buf1, p, rbase, c0);  // k3
#pragma unroll
        for (int ri = 0; ri < 4; ri++)
#pragma unroll
            for (int c = 0; c < 2; c++) {
                ksum[ri][c] = k1v[ri][c] + 3.0f * (k2v[ri][c] + kv[ri][c]);
                y[ri][c] = fmaf(dt, k1v[ri][c] - k2v[ri][c] + kv[ri][c], h[ri][c]);
            }

        feval2(y, kv, W1t, W2t, bb1, bb2, buf0, buf1, p, rbase, c0);  // k4
        const float dt8 = dt * 0.125f;
#pragma unroll
        for (int ri = 0; ri < 4; ri++)
#pragma unroll
            for (int c = 0; c < 2; c++)
                h[ri][c] = fmaf(dt8, ksum[ri][c] + kv[ri][c], h[ri][c]);
    }

    // ---- out = h @ W_out^T + b_out ----
    __syncthreads();  // all GEMM readers done before buf0/W1t reuse
    {
        float hv[4][2];
#pragma unroll
        for (int ri = 0; ri < 4; ri++) { hv[ri][0] = h[ri][0]; hv[ri][1] = h[ri][1]; }
        stage_dup(buf0, rbase, c0, hv);
    }
    for (int i = tid; i < D_OUT * H_SZ; i += NTHREADS) {
        const int j = i >> 7, k = i & 127;
        W1t[k * D_OUT + j] = W_out[i];
    }
    __syncthreads();

    const int col  = tid & 63;
    const int rowq = tid >> 6;
    float o[4];
#pragma unroll
    for (int ri = 0; ri < 4; ri++) o[ri] = __ldg(b_out + col);
#pragma unroll 8
    for (int k = 0; k < H_SZ; k++) {
        const float wv = W1t[k * D_OUT + col];
#pragma unroll
        for (int ri = 0; ri < 4; ri++)
            o[ri] = fmaf(buf0[(rowq * 4 + ri) * BSTRIDE + 2 * k], wv, o[ri]);
    }
#pragma unroll
    for (int ri = 0; ri < 4; ri++)
        out[(size_t)(b0 + rowq * 4 + ri) * D_OUT + col] = o[ri];
}

extern "C" void kernel_launch(void* const* d_in, const int* in_sizes, int n_in,
                              void* d_out, int out_size) {
    const float* x     = (const float*)d_in[0];
    const float* span  = (const float*)d_in[1];
    const float* W_emb = (const float*)d_in[2];
    const float* b_emb = (const float*)d_in[3];
    const float* W_ih  = (const float*)d_in[4];
    const float* b_ih  = (const float*)d_in[5];
    const float* W_hh  = (const float*)d_in[6];
    const float* b_hh  = (const float*)d_in[7];
    const float* W1    = (const float*)d_in[8];
    const float* b1    = (const float*)d_in[9];
    const float* W2    = (const float*)d_in[10];
    const float* b2    = (const float*)d_in[11];
    const float* W_out = (const float*)d_in[12];
    const float* b_out = (const float*)d_in[13];
    float* out = (float*)d_out;

    cudaFuncSetAttribute(rnnode_kernel,
                         cudaFuncAttributeMaxDynamicSharedMemorySize, SMEM_BYTES);
    rnnode_kernel<<<B_SZ / M_TILE, NTHREADS, SMEM_BYTES>>>(
        x, span, W_emb, b_emb, W_ih, b_ih, W_hh, b_hh,
        W1, b1, W2, b2, W_out, b_out, out);
}

// round 3
// speedup vs baseline: 1.7742x; 1.7742x over previous
#include <cuda_runtime.h>
#include <math.h>

#define B_SZ   2048
#define T_SZ   512
#define D_IN   64
#define H_SZ   128
#define D_OUT  64
#define M_TILE 16
#define NTHREADS 128
#define NSTEPS (T_SZ - 1)

#define WPAD 132   // padded weight row (floats) -> conflict-free spread LDS.128
#define APAD 20    // padded activation k-row (floats) -> conflict-free STS.128

// SMEM layout (floats):
//  [0      .. 16896)  Whh_p [128 j][WPAD]   (row j = W_hh[j][0..127], padded)
//  [16896  .. 33792)  W1_p
//  [33792  .. 50688)  W2_p   (Whh_p region reused post-loop for W_out)
//  [50688  .. 53248)  A0  [128 k][APAD]  col-major activations
//  [53248  .. 55808)  A1
//  [55808  .. 55936)  v_s
//  [55936  .. 56064)  c_s
//  [56064  .. 56192)  b1_s
//  [56192  .. 56320)  b2_s
//  [56320  .. 56352)  xs[2][16]
#define OFF_WHH 0
#define OFF_W1  16896
#define OFF_W2  33792
#define OFF_A0  50688
#define OFF_A1  53248
#define OFF_V   55808
#define OFF_C   55936
#define OFF_B1  56064
#define OFF_B2  56192
#define OFF_XS  56320
#define SMEM_FLOATS 56352
#define SMEM_BYTES  (SMEM_FLOATS * 4)   // 225408 <= 232448

typedef unsigned long long u64;

__device__ __forceinline__ u64 pk(float a, float b) {
    u64 r;
    asm("mov.b64 %0, {%1, %2};" : "=l"(r) : "f"(a), "f"(b));
    return r;
}
__device__ __forceinline__ void upk(u64 v, float& a, float& b) {
    asm("mov.b64 {%0, %1}, %2;" : "=f"(a), "=f"(b) : "l"(v));
}
__device__ __forceinline__ void ffma2(u64& d, u64 a, u64 b) {
    asm("fma.rn.f32x2 %0, %1, %2, %0;" : "+l"(d) : "l"(a), "l"(b));
}

// acc[p] (row-pair p = rows 2p,2p+1 of col j) += A(col-major) @ W row j.
// Wp = weight base + j*WPAD (thread-private column j).
__device__ __forceinline__ void gemmC(const float* __restrict__ Wp,
                                      const float* __restrict__ A,
                                      u64 acc[8]) {
#pragma unroll 2
    for (int k = 0; k < H_SZ; k += 4) {
        const float4 w4 = *reinterpret_cast<const float4*>(Wp + k);  // spread, packed
        u64 wd0 = pk(w4.x, w4.x);
        u64 wd1 = pk(w4.y, w4.y);
        u64 wd2 = pk(w4.z, w4.z);
        u64 wd3 = pk(w4.w, w4.w);
#pragma unroll
        for (int kk = 0; kk < 4; kk++) {
            const u64 wd = (kk == 0) ? wd0 : (kk == 1) ? wd1 : (kk == 2) ? wd2 : wd3;
            const float* ar = A + (k + kk) * APAD;   // warp-uniform address
            const ulonglong2 q0 = *reinterpret_cast<const ulonglong2*>(ar);
            const ulonglong2 q1 = *reinterpret_cast<const ulonglong2*>(ar + 4);
            const ulonglong2 q2 = *reinterpret_cast<const ulonglong2*>(ar + 8);
            const ulonglong2 q3 = *reinterpret_cast<const ulonglong2*>(ar + 12);
            ffma2(acc[0], q0.x, wd);
            ffma2(acc[1], q0.y, wd);
            ffma2(acc[2], q1.x, wd);
            ffma2(acc[3], q1.y, wd);
            ffma2(acc[4], q2.x, wd);
            ffma2(acc[5], q2.y, wd);
            ffma2(acc[6], q3.x, wd);
            ffma2(acc[7], q3.y, wd);
        }
    }
}

// Stage this thread's 16 values (activation column j) col-major: A[j][r], r=0..15.
__device__ __forceinline__ void stageC(float* __restrict__ A, int j,
                                       const float v[16]) {
    float* dst = A + j * APAD;
#pragma unroll
    for (int q = 0; q < 4; q++) {
        *reinterpret_cast<float4*>(dst + 4 * q) =
            make_float4(v[4 * q], v[4 * q + 1], v[4 * q + 2], v[4 * q + 3]);
    }
}

__device__ __forceinline__ float silu_f(float v) {
    return v / (1.0f + __expf(-v));
}

// out = f(in) = silu(in @ W1^T + b1) @ W2^T + b2   (per-thread column j)
__device__ __forceinline__ void fevalC(const float in[16], float out[16],
                                       const float* __restrict__ W1pj,
                                       const float* __restrict__ W2pj,
                                       u64 bb1, u64 bb2,
                                       float* __restrict__ A0,
                                       float* __restrict__ A1,
                                       int& p, int j) {
    float* Ap = p ? A1 : A0;
    stageC(Ap, j, in);
    __syncthreads();

    u64 acc[8];
#pragma unroll
    for (int q = 0; q < 8; q++) acc[q] = bb1;
    gemmC(W1pj, Ap, acc);

    float z[16];
#pragma unroll
    for (int q = 0; q < 8; q++) {
        upk(acc[q], z[2 * q], z[2 * q + 1]);
        z[2 * q]     = silu_f(z[2 * q]);
        z[2 * q + 1] = silu_f(z[2 * q + 1]);
    }

    p ^= 1;
    Ap = p ? A1 : A0;
    stageC(Ap, j, z);
    __syncthreads();

#pragma unroll
    for (int q = 0; q < 8; q++) acc[q] = bb2;
    gemmC(W2pj, Ap, acc);
#pragma unroll
    for (int q = 0; q < 8; q++) upk(acc[q], out[2 * q], out[2 * q + 1]);
    p ^= 1;
}

__global__ void __launch_bounds__(NTHREADS, 1)
rnnode_kernel(const float* __restrict__ x, const float* __restrict__ span,
              const float* __restrict__ W_emb, const float* __restrict__ b_emb,
              const float* __restrict__ W_ih, const float* __restrict__ b_ih,
              const float* __restrict__ W_hh, const float* __restrict__ b_hh,
              const float* __restrict__ W1, const float* __restrict__ b1,
              const float* __restrict__ W2, const float* __restrict__ b2,
              const float* __restrict__ W_out, const float* __restrict__ b_out,
              float* __restrict__ out) {
    extern __shared__ float sm[];
    float* Whh_p = sm + OFF_WHH;
    float* W1_p  = sm + OFF_W1;
    float* W2_p  = sm + OFF_W2;
    float* A0    = sm + OFF_A0;
    float* A1    = sm + OFF_A1;
    float* v_s   = sm + OFF_V;
    float* c_s   = sm + OFF_C;
    float* b1_s  = sm + OFF_B1;
    float* b2_s  = sm + OFF_B2;
    float* xs    = sm + OFF_XS;   // [2][16]

    const int tid = threadIdx.x;
    const int j   = tid;          // this thread's output column (0..127)
    const int b0  = blockIdx.x * M_TILE;

    // Padded weight copies (no transpose needed: row j is the k-vector).
    for (int i = tid; i < H_SZ * H_SZ; i += NTHREADS) {
        const int jj = i >> 7, k = i & 127;
        Whh_p[jj * WPAD + k] = W_hh[i];
        W1_p[jj * WPAD + k]  = W1[i];
        W2_p[jj * WPAD + k]  = W2[i];
    }
    // Fold input path: u[b,t,:] = x[b,t]*v + c, c absorbing b_ih + b_hh.
    {
        float vv = 0.0f, cc = 0.0f;
        for (int d = 0; d < D_IN; d++) {
            const float w = W_ih[j * D_IN + d];
            vv = fmaf(w, W_emb[d], vv);
            cc = fmaf(w, b_emb[d], cc);
        }
        v_s[j]  = vv;
        c_s[j]  = cc + b_ih[j] + b_hh[j];
        b1_s[j] = b1[j];
        b2_s[j] = b2[j];
    }
    // Prefetch x for t=0.
    if (tid < M_TILE) xs[tid] = x[(size_t)(b0 + tid) * T_SZ];
    __syncthreads();

    const float vj = v_s[j];
    const float cj = c_s[j];
    const u64 bb1 = pk(b1_s[j], b1_s[j]);
    const u64 bb2 = pk(b2_s[j], b2_s[j]);

    const float* Whh_pj = Whh_p + j * WPAD;
    const float* W1_pj  = W1_p + j * WPAD;
    const float* W2_pj  = W2_p + j * WPAD;

    float h[16];
#pragma unroll
    for (int r = 0; r < 16; r++) h[r] = 0.0f;

    int p = 0;

    for (int t = 0; t < NSTEPS; t++) {
        const float dt  = __ldg(span + t + 1) - __ldg(span + t);
        const float dt3 = dt * (1.0f / 3.0f);
        const int cur = t & 1, nxt = cur ^ 1;

        // ---- RNN jump: h = tanh(x*v + c + h @ W_hh^T) ----
        float* Ap = p ? A1 : A0;
        stageC(Ap, j, h);
        __syncthreads();

        // Prefetch next step's x (consumed next iter; syncs below order it).
        if (t + 1 < NSTEPS && tid < M_TILE)
            xs[nxt * 16 + tid] = x[(size_t)(b0 + tid) * T_SZ + (t + 1)];

        u64 acc[8];
#pragma unroll
        for (int q = 0; q < 8; q++) {
            acc[q] = pk(fmaf(xs[cur * 16 + 2 * q], vj, cj),
                        fmaf(xs[cur * 16 + 2 * q + 1], vj, cj));
        }
        gemmC(Whh_pj, Ap, acc);
        p ^= 1;
#pragma unroll
        for (int q = 0; q < 8; q++) {
            float a0, a1;
            upk(acc[q], a0, a1);
            h[2 * q]     = tanhf(a0);
            h[2 * q + 1] = tanhf(a1);
        }

        // ---- RK4 (3/8 rule) ----
        float k1v[16], kv[16], y[16], ksum[16];

        fevalC(h, k1v, W1_pj, W2_pj, bb1, bb2, A0, A1, p, j);
#pragma unroll
        for (int r = 0; r < 16; r++)
            y[r] = fmaf(dt3, k1v[r], h[r]);

        fevalC(y, kv, W1_pj, W2_pj, bb1, bb2, A0, A1, p, j);   // k2
#pragma unroll
        for (int r = 0; r < 16; r++) {
            ksum[r] = 3.0f * kv[r];
            y[r] = fmaf(dt, kv[r], fmaf(-dt3, k1v[r], h[r]));
            kv[r] = k1v[r] - kv[r];   // k1 - k2 (for k4 input)
        }

        fevalC(y, y, W1_pj, W2_pj, bb1, bb2, A0, A1, p, j);    // y now = k3
#pragma unroll
        for (int r = 0; r < 16; r++) {
            ksum[r] = k1v[r] + 3.0f * y[r] + ksum[r];          // k1 + 3(k2+k3)
            kv[r] = fmaf(dt, kv[r] + y[r], h[r]);              // h + dt(k1-k2+k3)
        }

        fevalC(kv, y, W1_pj, W2_pj, bb1, bb2, A0, A1, p, j);   // y = k4
        const float dt8 = dt * 0.125f;
#pragma unroll
        for (int r = 0; r < 16; r++)
            h[r] = fmaf(dt8, ksum[r] + y[r], h[r]);
    }

    // ---- out = h @ W_out^T + b_out ----
    __syncthreads();   // all GEMM readers done before weight-region reuse
    stageC(A0, j, h);
    for (int i = tid; i < D_OUT * H_SZ; i += NTHREADS) {
        const int jj = i >> 7, k = i & 127;
        Whh_p[jj * WPAD + k] = W_out[i];
    }
    __syncthreads();

    if (tid < D_OUT) {
        const int jo = tid;
        const float* Wo = Whh_p + jo * WPAD;
        float o[16];
        const float bo = __ldg(b_out + jo);
#pragma unroll
        for (int r = 0; r < 16; r++) o[r] = bo;
#pragma unroll 4
        for (int k = 0; k < H_SZ; k++) {
            const float wv = Wo[k];
            const float* ar = A0 + k * APAD;
#pragma unroll
            for (int r = 0; r < 16; r++)
                o[r] = fmaf(ar[r], wv, o[r]);
        }
#pragma unroll
        for (int r = 0; r < 16; r++)
            out[(size_t)(b0 + r) * D_OUT + jo] = o[r];
    }
}

extern "C" void kernel_launch(void* const* d_in, const int* in_sizes, int n_in,
                              void* d_out, int out_size) {
    const float* x     = (const float*)d_in[0];
    const float* span  = (const float*)d_in[1];
    const float* W_emb = (const float*)d_in[2];
    const float* b_emb = (const float*)d_in[3];
    const float* W_ih  = (const float*)d_in[4];
    const float* b_ih  = (const float*)d_in[5];
    const float* W_hh  = (const float*)d_in[6];
    const float* b_hh  = (const float*)d_in[7];
    const float* W1    = (const float*)d_in[8];
    const float* b1    = (const float*)d_in[9];
    const float* W2    = (const float*)d_in[10];
    const float* b2    = (const float*)d_in[11];
    const float* W_out = (const float*)d_in[12];
    const float* b_out = (const float*)d_in[13];
    float* out = (float*)d_out;

    cudaFuncSetAttribute(rnnode_kernel,
                         cudaFuncAttributeMaxDynamicSharedMemorySize, SMEM_BYTES);
    rnnode_kernel<<<B_SZ / M_TILE, NTHREADS, SMEM_BYTES>>>(
        x, span, W_emb, b_emb, W_ih, b_ih, W_hh, b_hh,
        W1, b1, W2, b2, W_out, b_out, out);
}

// round 4
// speedup vs baseline: 1.7744x; 1.0001x over previous
#include <cuda_runtime.h>
#include <math.h>

#define B_SZ   2048
#define T_SZ   512
#define D_IN   64
#define H_SZ   128
#define D_OUT  64
#define M_TILE 16
#define NTHREADS 128
#define NSTEPS (T_SZ - 1)

#define WPAD 132   // padded weight row (floats) -> conflict-free spread LDS.128
#define APAD 20    // padded activation k-row (floats) -> conflict-free STS.128

// SMEM layout (floats):
//  [0      .. 16896)  Whh_p [128 j][WPAD]   (row j = W_hh[j][0..127], padded)
//  [16896  .. 33792)  W1_p
//  [33792  .. 50688)  W2_p   (Whh_p region reused post-loop for W_out)
//  [50688  .. 53248)  A0  [128 k][APAD]  col-major activations
//  [53248  .. 55808)  A1
//  [55808  .. 55936)  v_s
//  [55936  .. 56064)  c_s
//  [56064  .. 56192)  b1_s
//  [56192  .. 56320)  b2_s
//  [56320  .. 56352)  xs[2][16]
#define OFF_WHH 0
#define OFF_W1  16896
#define OFF_W2  33792
#define OFF_A0  50688
#define OFF_A1  53248
#define OFF_V   55808
#define OFF_C   55936
#define OFF_B1  56064
#define OFF_B2  56192
#define OFF_XS  56320
#define SMEM_FLOATS 56352
#define SMEM_BYTES  (SMEM_FLOATS * 4)   // 225408 <= 232448

typedef unsigned long long u64;

__device__ __forceinline__ u64 pk(float a, float b) {
    u64 r;
    asm("mov.b64 %0, {%1, %2};" : "=l"(r) : "f"(a), "f"(b));
    return r;
}
__device__ __forceinline__ void upk(u64 v, float& a, float& b) {
    asm("mov.b64 {%0, %1}, %2;" : "=f"(a), "=f"(b) : "l"(v));
}
__device__ __forceinline__ void ffma2(u64& d, u64 a, u64 b) {
    asm("fma.rn.f32x2 %0, %1, %2, %0;" : "+l"(d) : "l"(a), "l"(b));
}

// acc[p] (row-pair p = rows 2p,2p+1 of col j) += A(col-major) @ W row j.
// Wp = weight base + j*WPAD (thread-private column j).
__device__ __forceinline__ void gemmC(const float* __restrict__ Wp,
                                      const float* __restrict__ A,
                                      u64 acc[8]) {
#pragma unroll 2
    for (int k = 0; k < H_SZ; k += 4) {
        const float4 w4 = *reinterpret_cast<const float4*>(Wp + k);  // spread, packed
        u64 wd0 = pk(w4.x, w4.x);
        u64 wd1 = pk(w4.y, w4.y);
        u64 wd2 = pk(w4.z, w4.z);
        u64 wd3 = pk(w4.w, w4.w);
#pragma unroll
        for (int kk = 0; kk < 4; kk++) {
            const u64 wd = (kk == 0) ? wd0 : (kk == 1) ? wd1 : (kk == 2) ? wd2 : wd3;
            const float* ar = A + (k + kk) * APAD;   // warp-uniform address
            const ulonglong2 q0 = *reinterpret_cast<const ulonglong2*>(ar);
            const ulonglong2 q1 = *reinterpret_cast<const ulonglong2*>(ar + 4);
            const ulonglong2 q2 = *reinterpret_cast<const ulonglong2*>(ar + 8);
            const ulonglong2 q3 = *reinterpret_cast<const ulonglong2*>(ar + 12);
            ffma2(acc[0], q0.x, wd);
            ffma2(acc[1], q0.y, wd);
            ffma2(acc[2], q1.x, wd);
            ffma2(acc[3], q1.y, wd);
            ffma2(acc[4], q2.x, wd);
            ffma2(acc[5], q2.y, wd);
            ffma2(acc[6], q3.x, wd);
            ffma2(acc[7], q3.y, wd);
        }
    }
}

// Stage this thread's 16 values (activation column j) col-major: A[j][r], r=0..15.
__device__ __forceinline__ void stageC(float* __restrict__ A, int j,
                                       const float v[16]) {
    float* dst = A + j * APAD;
#pragma unroll
    for (int q = 0; q < 4; q++) {
        *reinterpret_cast<float4*>(dst + 4 * q) =
            make_float4(v[4 * q], v[4 * q + 1], v[4 * q + 2], v[4 * q + 3]);
    }
}

__device__ __forceinline__ float silu_f(float v) {
    return v / (1.0f + __expf(-v));
}

// out = f(in) = silu(in @ W1^T + b1) @ W2^T + b2   (per-thread column j)
__device__ __forceinline__ void fevalC(const float in[16], float out[16],
                                       const float* __restrict__ W1pj,
                                       const float* __restrict__ W2pj,
                                       u64 bb1, u64 bb2,
                                       float* __restrict__ A0,
                                       float* __restrict__ A1,
                                       int& p, int j) {
    float* Ap = p ? A1 : A0;
    stageC(Ap, j, in);
    __syncthreads();

    u64 acc[8];
#pragma unroll
    for (int q = 0; q < 8; q++) acc[q] = bb1;
    gemmC(W1pj, Ap, acc);

    float z[16];
#pragma unroll
    for (int q = 0; q < 8; q++) {
        upk(acc[q], z[2 * q], z[2 * q + 1]);
        z[2 * q]     = silu_f(z[2 * q]);
        z[2 * q + 1] = silu_f(z[2 * q + 1]);
    }

    p ^= 1;
    Ap = p ? A1 : A0;
    stageC(Ap, j, z);
    __syncthreads();

#pragma unroll
    for (int q = 0; q < 8; q++) acc[q] = bb2;
    gemmC(W2pj, Ap, acc);
#pragma unroll
    for (int q = 0; q < 8; q++) upk(acc[q], out[2 * q], out[2 * q + 1]);
    p ^= 1;
}

__global__ void __launch_bounds__(NTHREADS, 1)
rnnode_kernel(const float* __restrict__ x, const float* __restrict__ span,
              const float* __restrict__ W_emb, const float* __restrict__ b_emb,
              const float* __restrict__ W_ih, const float* __restrict__ b_ih,
              const float* __restrict__ W_hh, const float* __restrict__ b_hh,
              const float* __restrict__ W1, const float* __restrict__ b1,
              const float* __restrict__ W2, const float* __restrict__ b2,
              const float* __restrict__ W_out, const float* __restrict__ b_out,
              float* __restrict__ out) {
    extern __shared__ float sm[];
    float* Whh_p = sm + OFF_WHH;
    float* W1_p  = sm + OFF_W1;
    float* W2_p  = sm + OFF_W2;
    float* A0    = sm + OFF_A0;
    float* A1    = sm + OFF_A1;
    float* v_s   = sm + OFF_V;
    float* c_s   = sm + OFF_C;
    float* b1_s  = sm + OFF_B1;
    float* b2_s  = sm + OFF_B2;
    float* xs    = sm + OFF_XS;   // [2][16]

    const int tid = threadIdx.x;
    const int j   = tid;          // this thread's output column (0..127)
    const int b0  = blockIdx.x * M_TILE;

    // Padded weight copies (no transpose needed: row j is the k-vector).
    for (int i = tid; i < H_SZ * H_SZ; i += NTHREADS) {
        const int jj = i >> 7, k = i & 127;
        Whh_p[jj * WPAD + k] = W_hh[i];
        W1_p[jj * WPAD + k]  = W1[i];
        W2_p[jj * WPAD + k]  = W2[i];
    }
    // Fold input path: u[b,t,:] = x[b,t]*v + c, c absorbing b_ih + b_hh.
    {
        float vv = 0.0f, cc = 0.0f;
        for (int d = 0; d < D_IN; d++) {
            const float w = W_ih[j * D_IN + d];
            vv = fmaf(w, W_emb[d], vv);
            cc = fmaf(w, b_emb[d], cc);
        }
        v_s[j]  = vv;
        c_s[j]  = cc + b_ih[j] + b_hh[j];
        b1_s[j] = b1[j];
        b2_s[j] = b2[j];
    }
    // Prefetch x for t=0.
    if (tid < M_TILE) xs[tid] = x[(size_t)(b0 + tid) * T_SZ];
    __syncthreads();

    const float vj = v_s[j];
    const float cj = c_s[j];
    const u64 bb1 = pk(b1_s[j], b1_s[j]);
    const u64 bb2 = pk(b2_s[j], b2_s[j]);

    const float* Whh_pj = Whh_p + j * WPAD;
    const float* W1_pj  = W1_p + j * WPAD;
    const float* W2_pj  = W2_p + j * WPAD;

    float h[16];
#pragma unroll
    for (int r = 0; r < 16; r++) h[r] = 0.0f;

    int p = 0;

    for (int t = 0; t < NSTEPS; t++) {
        const float dt  = __ldg(span + t + 1) - __ldg(span + t);
        const float dt3 = dt * (1.0f / 3.0f);
        const int cur = t & 1, nxt = cur ^ 1;

        // ---- RNN jump: h = tanh(x*v + c + h @ W_hh^T) ----
        float* Ap = p ? A1 : A0;
        stageC(Ap, j, h);
        __syncthreads();

        // Prefetch next step's x (consumed next iter; syncs below order it).
        if (t + 1 < NSTEPS && tid < M_TILE)
            xs[nxt * 16 + tid] = x[(size_t)(b0 + tid) * T_SZ + (t + 1)];

        u64 acc[8];
#pragma unroll
        for (int q = 0; q < 8; q++) {
            acc[q] = pk(fmaf(xs[cur * 16 + 2 * q], vj, cj),
                        fmaf(xs[cur * 16 + 2 * q + 1], vj, cj));
        }
        gemmC(Whh_pj, Ap, acc);
        p ^= 1;
#pragma unroll
        for (int q = 0; q < 8; q++) {
            float a0, a1;
            upk(acc[q], a0, a1);
            h[2 * q]     = tanhf(a0);
            h[2 * q + 1] = tanhf(a1);
        }

        // ---- RK4 (3/8 rule) ----
        float k1v[16], kv[16], y[16], ksum[16];

        fevalC(h, k1v, W1_pj, W2_pj, bb1, bb2, A0, A1, p, j);
#pragma unroll
        for (int r = 0; r < 16; r++)
            y[r] = fmaf(dt3, k1v[r], h[r]);

        fevalC(y, kv, W1_pj, W2_pj, bb1, bb2, A0, A1, p, j);   // k2
#pragma unroll
        for (int r = 0; r < 16; r++) {
            ksum[r] = 3.0f * kv[r];
            y[r] = fmaf(dt, kv[r], fmaf(-dt3, k1v[r], h[r]));
            kv[r] = k1v[r] - kv[r];   // k1 - k2 (for k4 input)
        }

        fevalC(y, y, W1_pj, W2_pj, bb1, bb2, A0, A1, p, j);    // y now = k3
#pragma unroll
        for (int r = 0; r < 16; r++) {
            ksum[r] = k1v[r] + 3.0f * y[r] + ksum[r];          // k1 + 3(k2+k3)
            kv[r] = fmaf(dt, kv[r] + y[r], h[r]);              // h + dt(k1-k2+k3)
        }

        fevalC(kv, y, W1_pj, W2_pj, bb1, bb2, A0, A1, p, j);   // y = k4
        const float dt8 = dt * 0.125f;
#pragma unroll
        for (int r = 0; r < 16; r++)
            h[r] = fmaf(dt8, ksum[r] + y[r], h[r]);
    }

    // ---- out = h @ W_out^T + b_out ----
    __syncthreads();   // all GEMM readers done before weight-region reuse
    stageC(A0, j, h);
    for (int i = tid; i < D_OUT * H_SZ; i += NTHREADS) {
        const int jj = i >> 7, k = i & 127;
        Whh_p[jj * WPAD + k] = W_out[i];
    }
    __syncthreads();

    if (tid < D_OUT) {
        const int jo = tid;
        const float* Wo = Whh_p + jo * WPAD;
        float o[16];
        const float bo = __ldg(b_out + jo);
#pragma unroll
        for (int r = 0; r < 16; r++) o[r] = bo;
#pragma unroll 4
        for (int k = 0; k < H_SZ; k++) {
            const float wv = Wo[k];
            const float* ar = A0 + k * APAD;
#pragma unroll
            for (int r = 0; r < 16; r++)
                o[r] = fmaf(ar[r], wv, o[r]);
        }
#pragma unroll
        for (int r = 0; r < 16; r++)
            out[(size_t)(b0 + r) * D_OUT + jo] = o[r];
    }
}

extern "C" void kernel_launch(void* const* d_in, const int* in_sizes, int n_in,
                              void* d_out, int out_size) {
    const float* x     = (const float*)d_in[0];
    const float* span  = (const float*)d_in[1];
    const float* W_emb = (const float*)d_in[2];
    const float* b_emb = (const float*)d_in[3];
    const float* W_ih  = (const float*)d_in[4];
    const float* b_ih  = (const float*)d_in[5];
    const float* W_hh  = (const float*)d_in[6];
    const float* b_hh  = (const float*)d_in[7];
    const float* W1    = (const float*)d_in[8];
    const float* b1    = (const float*)d_in[9];
    const float* W2    = (const float*)d_in[10];
    const float* b2    = (const float*)d_in[11];
    const float* W_out = (const float*)d_in[12];
    const float* b_out = (const float*)d_in[13];
    float* out = (float*)d_out;

    cudaFuncSetAttribute(rnnode_kernel,
                         cudaFuncAttributeMaxDynamicSharedMemorySize, SMEM_BYTES);
    rnnode_kernel<<<B_SZ / M_TILE, NTHREADS, SMEM_BYTES>>>(
        x, span, W_emb, b_emb, W_ih, b_ih, W_hh, b_hh,
        W1, b1, W2, b2, W_out, b_out, out);
}

// round 5
// speedup vs baseline: 2.6242x; 1.4789x over previous
#include <cuda_runtime.h>
#include <math.h>

#define B_SZ   2048
#define T_SZ   512
#define D_IN   64
#define H_SZ   128
#define D_OUT  64
#define M_TILE 16
#define NTHREADS 128
#define NSTEPS (T_SZ - 1)

// SMEM layout (floats):
//  [0      .. 16384)  Whh_t  (k-major: Whh_t[k*H+j] = W_hh[j*H+k])
//  [16384  .. 32768)  W1t    (reused post-loop for W_out_t)
//  [32768  .. 49152)  Pt     (k-major P^T view: Pt[k*H+j] = P[j][k], P = W1@W2)
//  [49152  .. 51200)  buf0   [16][128]
//  [51200  .. 53248)  buf1   [16][128]
//  [53248  .. 53376)  v_s
//  [53376  .. 53504)  c_s
//  [53504  .. 53632)  b1_s
//  [53632  .. 53760)  b2_s
//  [53760  .. 53888)  c1_s   (b2 @ W1^T)
//  [53888  .. 53904)  xs
#define OFF_WHH 0
#define OFF_W1  16384
#define OFF_P   32768
#define OFF_B0  49152
#define OFF_B1  51200
#define OFF_V   53248
#define OFF_C   53376
#define OFF_BB1 53504
#define OFF_BB2 53632
#define OFF_C1  53760
#define OFF_XS  53888
#define SMEM_FLOATS 53904
#define SMEM_BYTES  (SMEM_FLOATS * 4)   // 215616 B

// Precomputed by prep_kernel:
__device__ float g_P[H_SZ * H_SZ];    // g_P[k*H+j]   = sum_m W1[j][m] * W2[m][k]
__device__ float g_W2t[H_SZ * H_SZ];  // g_W2t[k*H+j] = W2[j][k]

__global__ void prep_kernel(const float* __restrict__ W1,
                            const float* __restrict__ W2) {
    __shared__ float w1row[H_SZ];
    const int j = blockIdx.x;
    const int k = threadIdx.x;
    w1row[k] = W1[j * H_SZ + k];
    __syncthreads();
    float s = 0.0f;
#pragma unroll 8
    for (int m = 0; m < H_SZ; m++)
        s = fmaf(w1row[m], W2[m * H_SZ + k], s);
    g_P[k * H_SZ + j]   = s;
    g_W2t[k * H_SZ + j] = W2[j * H_SZ + k];
}

__device__ __forceinline__ void gemm_acc(const float* __restrict__ Wt,
                                         const float* __restrict__ bufp,
                                         int rbase, int j0, float acc[4][4]) {
#pragma unroll 8
    for (int k = 0; k < H_SZ; k += 4) {
        const float4 w0 = *reinterpret_cast<const float4*>(Wt + (k + 0) * H_SZ + j0);
        const float4 w1 = *reinterpret_cast<const float4*>(Wt + (k + 1) * H_SZ + j0);
        const float4 w2 = *reinterpret_cast<const float4*>(Wt + (k + 2) * H_SZ + j0);
        const float4 w3 = *reinterpret_cast<const float4*>(Wt + (k + 3) * H_SZ + j0);
#pragma unroll
        for (int ri = 0; ri < 4; ri++) {
            const float4 a = *reinterpret_cast<const float4*>(bufp + (rbase + ri) * H_SZ + k);
            acc[ri][0] = fmaf(a.x, w0.x, acc[ri][0]);
            acc[ri][1] = fmaf(a.x, w0.y, acc[ri][1]);
            acc[ri][2] = fmaf(a.x, w0.z, acc[ri][2]);
            acc[ri][3] = fmaf(a.x, w0.w, acc[ri][3]);
            acc[ri][0] = fmaf(a.y, w1.x, acc[ri][0]);
            acc[ri][1] = fmaf(a.y, w1.y, acc[ri][1]);
            acc[ri][2] = fmaf(a.y, w1.z, acc[ri][2]);
            acc[ri][3] = fmaf(a.y, w1.w, acc[ri][3]);
            acc[ri][0] = fmaf(a.z, w2.x, acc[ri][0]);
            acc[ri][1] = fmaf(a.z, w2.y, acc[ri][1]);
            acc[ri][2] = fmaf(a.z, w2.z, acc[ri][2]);
            acc[ri][3] = fmaf(a.z, w2.w, acc[ri][3]);
            acc[ri][0] = fmaf(a.w, w3.x, acc[ri][0]);
            acc[ri][1] = fmaf(a.w, w3.y, acc[ri][1]);
            acc[ri][2] = fmaf(a.w, w3.z, acc[ri][2]);
            acc[ri][3] = fmaf(a.w, w3.w, acc[ri][3]);
        }
    }
}

// Same, but weights streamed from global (L2-resident).
__device__ __forceinline__ void gemm_acc_glb(const float* __restrict__ Wt,
                                             const float* __restrict__ bufp,
                                             int rbase, int j0, float acc[4][4]) {
#pragma unroll 8
    for (int k = 0; k < H_SZ; k += 4) {
        const float4 w0 = __ldg(reinterpret_cast<const float4*>(Wt + (k + 0) * H_SZ + j0));
        const float4 w1 = __ldg(reinterpret_cast<const float4*>(Wt + (k + 1) * H_SZ + j0));
        const float4 w2 = __ldg(reinterpret_cast<const float4*>(Wt + (k + 2) * H_SZ + j0));
        const float4 w3 = __ldg(reinterpret_cast<const float4*>(Wt + (k + 3) * H_SZ + j0));
#pragma unroll
        for (int ri = 0; ri < 4; ri++) {
            const float4 a = *reinterpret_cast<const float4*>(bufp + (rbase + ri) * H_SZ + k);
            acc[ri][0] = fmaf(a.x, w0.x, acc[ri][0]);
            acc[ri][1] = fmaf(a.x, w0.y, acc[ri][1]);
            acc[ri][2] = fmaf(a.x, w0.z, acc[ri][2]);
            acc[ri][3] = fmaf(a.x, w0.w, acc[ri][3]);
            acc[ri][0] = fmaf(a.y, w1.x, acc[ri][0]);
            acc[ri][1] = fmaf(a.y, w1.y, acc[ri][1]);
            acc[ri][2] = fmaf(a.y, w1.z, acc[ri][2]);
            acc[ri][3] = fmaf(a.y, w1.w, acc[ri][3]);
            acc[ri][0] = fmaf(a.z, w2.x, acc[ri][0]);
            acc[ri][1] = fmaf(a.z, w2.y, acc[ri][1]);
            acc[ri][2] = fmaf(a.z, w2.z, acc[ri][2]);
            acc[ri][3] = fmaf(a.z, w2.w, acc[ri][3]);
            acc[ri][0] = fmaf(a.w, w3.x, acc[ri][0]);
            acc[ri][1] = fmaf(a.w, w3.y, acc[ri][1]);
            acc[ri][2] = fmaf(a.w, w3.z, acc[ri][2]);
            acc[ri][3] = fmaf(a.w, w3.w, acc[ri][3]);
        }
    }
}

__device__ __forceinline__ void stage4(float* __restrict__ bufp, int rbase, int j0,
                                       const float v[4][4]) {
#pragma unroll
    for (int ri = 0; ri < 4; ri++) {
        *reinterpret_cast<float4*>(bufp + (rbase + ri) * H_SZ + j0) =
            make_float4(v[ri][0], v[ri][1], v[ri][2], v[ri][3]);
    }
}

__device__ __forceinline__ float silu_f(float v) {
    return v / (1.0f + __expf(-v));
}

__global__ void __launch_bounds__(NTHREADS, 1)
rnnode_kernel(const float* __restrict__ x, const float* __restrict__ span,
              const float* __restrict__ W_emb, const float* __restrict__ b_emb,
              const float* __restrict__ W_ih, const float* __restrict__ b_ih,
              const float* __restrict__ W_hh, const float* __restrict__ b_hh,
              const float* __restrict__ W1, const float* __restrict__ b1,
              const float* __restrict__ W2, const float* __restrict__ b2,
              const float* __restrict__ W_out, const float* __restrict__ b_out,
              float* __restrict__ out) {
    extern __shared__ float sm[];
    float* Whh_t = sm + OFF_WHH;
    float* W1t   = sm + OFF_W1;
    float* Pt    = sm + OFF_P;
    float* buf0  = sm + OFF_B0;
    float* buf1  = sm + OFF_B1;
    float* v_s   = sm + OFF_V;
    float* c_s   = sm + OFF_C;
    float* b1_s  = sm + OFF_BB1;
    float* b2_s  = sm + OFF_BB2;
    float* c1_s  = sm + OFF_C1;
    float* xs    = sm + OFF_XS;

    const int tid = threadIdx.x;
    const int b0  = blockIdx.x * M_TILE;

    // Load weights transposed to k-major; P already k-major in global.
    for (int i = tid; i < H_SZ * H_SZ; i += NTHREADS) {
        const int j = i >> 7, k = i & 127;
        Whh_t[k * H_SZ + j] = W_hh[i];
        W1t[k * H_SZ + j]   = W1[i];
        Pt[i] = g_P[i];
    }
    // Fold input path + aux vectors.
    if (tid < H_SZ) {
        float vv = 0.0f, cc = 0.0f;
        for (int d = 0; d < D_IN; d++) {
            const float w = W_ih[tid * D_IN + d];
            vv = fmaf(w, W_emb[d], vv);
            cc = fmaf(w, b_emb[d], cc);
        }
        v_s[tid]  = vv;
        c_s[tid]  = cc + b_ih[tid] + b_hh[tid];
        b1_s[tid] = b1[tid];
        b2_s[tid] = b2[tid];
        // c1 = b2 @ W1^T : c1[j] = sum_k b2[k] * W1[j][k]
        float c1v = 0.0f;
        for (int k = 0; k < H_SZ; k++)
            c1v = fmaf(b2[k], W1[tid * H_SZ + k], c1v);
        c1_s[tid] = c1v;
    }
    __syncthreads();

    const int rg    = tid >> 5;
    const int lane  = tid & 31;
    const int rbase = rg * 4;
    const int j0    = lane * 4;

    const float4 b1v = *reinterpret_cast<const float4*>(b1_s + j0);
    const float4 b2v = *reinterpret_cast<const float4*>(b2_s + j0);
    const float4 c1v = *reinterpret_cast<const float4*>(c1_s + j0);
    const float4 vv  = *reinterpret_cast<const float4*>(v_s + j0);
    const float4 cc  = *reinterpret_cast<const float4*>(c_s + j0);
    const float b1a[4] = {b1v.x, b1v.y, b1v.z, b1v.w};
    const float b2a[4] = {b2v.x, b2v.y, b2v.z, b2v.w};
    const float c1a[4] = {c1v.x, c1v.y, c1v.z, c1v.w};

    float h[4][4];
#pragma unroll
    for (int ri = 0; ri < 4; ri++)
#pragma unroll
        for (int c = 0; c < 4; c++) h[ri][c] = 0.0f;

    int p = 0;
#define BUF(pp) ((pp) ? buf1 : buf0)

    for (int t = 0; t < NSTEPS; t++) {
        const float dt   = __ldg(span + t + 1) - __ldg(span + t);
        const float dt3  = dt * (1.0f / 3.0f);
        const float dt23 = dt3 * 2.0f;
        const float dt8  = dt * 0.125f;

        float acc[4][4];
        float z1[4][4], u1[4][4], u2[4][4], u3[4][4];

        // ---- G1: h = tanh(x*v + c + h @ Whh^T) ----
        stage4(BUF(p), rbase, j0, h);
        if (tid < M_TILE) xs[tid] = x[(size_t)(b0 + tid) * T_SZ + t];
        __syncthreads();
#pragma unroll
        for (int ri = 0; ri < 4; ri++) {
            const float xv = xs[rbase + ri];
            acc[ri][0] = fmaf(xv, vv.x, cc.x);
            acc[ri][1] = fmaf(xv, vv.y, cc.y);
            acc[ri][2] = fmaf(xv, vv.z, cc.z);
            acc[ri][3] = fmaf(xv, vv.w, cc.w);
        }
        gemm_acc(Whh_t, BUF(p), rbase, j0, acc);
        p ^= 1;
#pragma unroll
        for (int ri = 0; ri < 4; ri++)
#pragma unroll
            for (int c = 0; c < 4; c++) h[ri][c] = tanhf(acc[ri][c]);

        // ---- G2: z1 = h @ W1^T + b1 ; u1 = silu(z1) ----
        stage4(BUF(p), rbase, j0, h);
        __syncthreads();
#pragma unroll
        for (int ri = 0; ri < 4; ri++)
#pragma unroll
            for (int c = 0; c < 4; c++) acc[ri][c] = b1a[c];
        gemm_acc(W1t, BUF(p), rbase, j0, acc);
        p ^= 1;
#pragma unroll
        for (int ri = 0; ri < 4; ri++)
#pragma unroll
            for (int c = 0; c < 4; c++) {
                z1[ri][c] = acc[ri][c];
                u1[ri][c] = silu_f(acc[ri][c]);
            }

        // ---- G3: z2 = z1 + dt/3*(u1 @ P^T + c1) ; u2 = silu(z2) ----
        stage4(BUF(p), rbase, j0, u1);
        __syncthreads();
#pragma unroll
        for (int ri = 0; ri < 4; ri++)
#pragma unroll
            for (int c = 0; c < 4; c++) acc[ri][c] = c1a[c];
        gemm_acc(Pt, BUF(p), rbase, j0, acc);
        p ^= 1;
#pragma unroll
        for (int ri = 0; ri < 4; ri++)
#pragma unroll
            for (int c = 0; c < 4; c++)
                u2[ri][c] = silu_f(fmaf(dt3, acc[ri][c], z1[ri][c]));

        // ---- G4: z3 = z1 + dt*((u2 - u1/3) @ P^T) + (2dt/3)*c1 ; u3 ----
        {
            float g2[4][4];
#pragma unroll
            for (int ri = 0; ri < 4; ri++)
#pragma unroll
                for (int c = 0; c < 4; c++)
                    g2[ri][c] = fmaf(-(1.0f / 3.0f), u1[ri][c], u2[ri][c]);
            stage4(BUF(p), rbase, j0, g2);
        }
        __syncthreads();
#pragma unroll
        for (int ri = 0; ri < 4; ri++)
#pragma unroll
            for (int c = 0; c < 4; c++) acc[ri][c] = 0.0f;
        gemm_acc(Pt, BUF(p), rbase, j0, acc);
        p ^= 1;
#pragma unroll
        for (int ri = 0; ri < 4; ri++)
#pragma unroll
            for (int c = 0; c < 4; c++)
                u3[ri][c] = silu_f(fmaf(dt, acc[ri][c],
                                        fmaf(dt23, c1a[c], z1[ri][c])));

        // ---- G5: z4 = z1 + dt*((u1 - u2 + u3) @ P^T + c1) ; u4 -> g4 ----
        {
            float g3[4][4];
#pragma unroll
            for (int ri = 0; ri < 4; ri++)
#pragma unroll
                for (int c = 0; c < 4; c++)
                    g3[ri][c] = u1[ri][c] - u2[ri][c] + u3[ri][c];
            stage4(BUF(p), rbase, j0, g3);
        }
        __syncthreads();
#pragma unroll
        for (int ri = 0; ri < 4; ri++)
#pragma unroll
            for (int c = 0; c < 4; c++) acc[ri][c] = c1a[c];
        gemm_acc(Pt, BUF(p), rbase, j0, acc);
        p ^= 1;

        // ---- G6: h += (dt/8)*(g4 @ W2^T) + dt*b2, g4 = u1+3(u2+u3)+u4 ----
        {
            float g4[4][4];
#pragma unroll
            for (int ri = 0; ri < 4; ri++)
#pragma unroll
                for (int c = 0; c < 4; c++) {
                    const float z4 = fmaf(dt, acc[ri][c], z1[ri][c]);
                    const float u4 = silu_f(z4);
                    g4[ri][c] = fmaf(3.0f, u2[ri][c] + u3[ri][c],
                                     u1[ri][c] + u4);
                }
            stage4(BUF(p), rbase, j0, g4);
        }
        __syncthreads();
#pragma unroll
        for (int ri = 0; ri < 4; ri++)
#pragma unroll
            for (int c = 0; c < 4; c++) acc[ri][c] = 0.0f;
        gemm_acc_glb(g_W2t, BUF(p), rbase, j0, acc);
        p ^= 1;
#pragma unroll
        for (int ri = 0; ri < 4; ri++)
#pragma unroll
            for (int c = 0; c < 4; c++)
                h[ri][c] = fmaf(dt8, acc[ri][c],
                                fmaf(dt, b2a[c], h[ri][c]));
    }

    // ---- out = h @ W_out^T + b_out ----
    __syncthreads();
    for (int i = tid; i < D_OUT * H_SZ; i += NTHREADS) {
        const int j = i >> 7, k = i & 127;
        W1t[k * D_OUT + j] = W_out[i];
    }
    float* bp = BUF(p);
    stage4(bp, rbase, j0, h);
    __syncthreads();

    const int jo = lane * 2;
#pragma unroll
    for (int ri = 0; ri < 4; ri++) {
        float o0 = __ldg(b_out + jo);
        float o1 = __ldg(b_out + jo + 1);
        const float* br = bp + (rbase + ri) * H_SZ;
#pragma unroll 16
        for (int k = 0; k < H_SZ; k++) {
            const float a = br[k];
            const float2 w = *reinterpret_cast<const float2*>(W1t + k * D_OUT + jo);
            o0 = fmaf(a, w.x, o0);
            o1 = fmaf(a, w.y, o1);
        }
        *reinterpret_cast<float2*>(out + (size_t)(b0 + rbase + ri) * D_OUT + jo) =
            make_float2(o0, o1);
    }
}

extern "C" void kernel_launch(void* const* d_in, const int* in_sizes, int n_in,
                              void* d_out, int out_size) {
    const float* x     = (const float*)d_in[0];
    const float* span  = (const float*)d_in[1];
    const float* W_emb = (const float*)d_in[2];
    const float* b_emb = (const float*)d_in[3];
    const float* W_ih  = (const float*)d_in[4];
    const float* b_ih  = (const float*)d_in[5];
    const float* W_hh  = (const float*)d_in[6];
    const float* b_hh  = (const float*)d_in[7];
    const float* W1    = (const float*)d_in[8];
    const float* b1    = (const float*)d_in[9];
    const float* W2    = (const float*)d_in[10];
    const float* b2    = (const float*)d_in[11];
    const float* W_out = (const float*)d_in[12];
    const float* b_out = (const float*)d_in[13];
    float* out = (float*)d_out;

    prep_kernel<<<H_SZ, H_SZ>>>(W1, W2);
    cudaFuncSetAttribute(rnnode_kernel,
                         cudaFuncAttributeMaxDynamicSharedMemorySize, SMEM_BYTES);
    rnnode_kernel<<<B_SZ / M_TILE, NTHREADS, SMEM_BYTES>>>(
        x, span, W_emb, b_emb, W_ih, b_ih, W_hh, b_hh,
        W1, b1, W2, b2, W_out, b_out, out);
}